// round 7
// baseline (speedup 1.0000x reference)
#include <cuda_runtime.h>
#include <cstdint>
#include <math.h>

#define NH 8
#define NN 2048
#define BM 64
#define NTILE 32
#define PDT 68

typedef unsigned long long u64;

// ---------------- smem word-offsets for k_attn ----------------
#define F_QHI  0          /* 4 strips x 8ks x 32 x 4 = 4096 */
#define F_QLO  4096
#define F_THI  8192
#define F_TLO  12288
#define F_KHI  16384      /* 64 x 68 = 4352 */
#define F_KLO  20736
#define F_KHHI 25088
#define F_KHLO 29440
#define F_VHI  33792      /* 64 x 72 = 4608 */
#define F_VLO  38400
#define F_CTRL 43008      /* [0,1]=mask ballot, [2..9]=warp counts */
#define SMEM_ATTN ((43008 + 16) * 4)   /* 172096 B */
#define F_EHI  F_KHI      /* E spill aliases dead K tiles during PV */
#define F_ELO  F_KHHI
#define F_LX   F_KLO      /* L cross-warp exchange (epilogue only) */

// ---------------- helpers ----------------
__device__ __forceinline__ uint32_t tfr(float x) {
    uint32_t r; asm("cvt.rna.tf32.f32 %0, %1;" : "=r"(r) : "f"(x)); return r;
}
__device__ __forceinline__ uint32_t tfhi(float x) { return __float_as_uint(x) & 0xffffe000u; }
__device__ __forceinline__ uint32_t tflo(float x) {
    return tfr(x - __uint_as_float(__float_as_uint(x) & 0xffffe000u));
}
__device__ __forceinline__ void mma8(float c[4], uint32_t a0, uint32_t a1, uint32_t a2, uint32_t a3,
                                     uint32_t b0, uint32_t b1) {
    asm volatile(
        "mma.sync.aligned.m16n8k8.row.col.f32.tf32.tf32.f32 "
        "{%0,%1,%2,%3},{%4,%5,%6,%7},{%8,%9},{%0,%1,%2,%3};"
        : "+f"(c[0]), "+f"(c[1]), "+f"(c[2]), "+f"(c[3])
        : "r"(a0), "r"(a1), "r"(a2), "r"(a3), "r"(b0), "r"(b1));
}

// -------- device scratch --------
__device__ float g_S[NH * 64 * 64];
__device__ float g_T[NH * NN * 64];
__device__ float g_KH[NH * NN * 64];
__device__ unsigned int g_cnt[NH];

// ============================================================
// Kernel A: S = softmax over flattened k*k of clusters @ clusters^T
// ============================================================
__global__ void k_clusterS(const float* __restrict__ clusters) {
    __shared__ float cl[64 * 64];
    __shared__ float ds[64 * 64];
    __shared__ float red[256];
    const int h = blockIdx.x, t = threadIdx.x;
    for (int i = t; i < 4096; i += 256) cl[i] = clusters[(size_t)h * 4096 + i];
    __syncthreads();
    float lmax = -1e30f;
    for (int i = t; i < 4096; i += 256) {
        const int kk = i >> 6, jj = i & 63;
        float s = 0.f;
#pragma unroll 16
        for (int d = 0; d < 64; d++) s += cl[kk * 64 + d] * cl[jj * 64 + d];
        ds[i] = s;
        lmax = fmaxf(lmax, s);
    }
    red[t] = lmax;
    __syncthreads();
    for (int o = 128; o > 0; o >>= 1) { if (t < o) red[t] = fmaxf(red[t], red[t + o]); __syncthreads(); }
    const float mx = red[0];
    __syncthreads();
    float lsum = 0.f;
    for (int i = t; i < 4096; i += 256) { const float e = expf(ds[i] - mx); ds[i] = e; lsum += e; }
    red[t] = lsum;
    __syncthreads();
    for (int o = 128; o > 0; o >>= 1) { if (t < o) red[t] += red[t + o]; __syncthreads(); }
    const float inv = 1.f / red[0];
    for (int i = t; i < 4096; i += 256) g_S[(size_t)h * 4096 + i] = ds[i] * inv;
    if (t == 0) g_cnt[h] = 0u;
}

// ============================================================
// k-major 64^3 SIMT GEMM helper for k_projhat (exact fp32)
// ============================================================
__device__ __forceinline__ void gemmT(const float* __restrict__ AT, const float* __restrict__ WT,
                                      int i0, int o0, float out[16]) {
    float acc[16];
#pragma unroll
    for (int q = 0; q < 16; q++) acc[q] = 0.f;
#pragma unroll 8
    for (int k = 0; k < 64; k++) {
        const float4 a = *(const float4*)&AT[k * PDT + i0];
        const float4 w = *(const float4*)&WT[k * PDT + o0];
        const float av[4] = {a.x, a.y, a.z, a.w};
        const float wv[4] = {w.x, w.y, w.z, w.w};
#pragma unroll
        for (int ii = 0; ii < 4; ii++)
#pragma unroll
            for (int jj = 0; jj < 4; jj++) acc[ii * 4 + jj] += av[ii] * wv[jj];
    }
#pragma unroll
    for (int q = 0; q < 16; q++) out[q] = acc[q];
}

__global__ void __launch_bounds__(256) k_projhat(
    const float* __restrict__ Qin, const float* __restrict__ Kin,
    const float* __restrict__ clusters, const float* __restrict__ W1,
    const float* __restrict__ b1, const float* __restrict__ W2,
    const float* __restrict__ b2) {
    extern __shared__ float smb[];
    float* AT = smb;
    float* BT = smb + 64 * PDT;
    float* WT = smb + 2 * 64 * PDT;
    const int t = threadIdx.x;
    const int h = blockIdx.y;
    const int row0 = blockIdx.x * 64;
    const int isK = blockIdx.z;
    const int ti = t >> 4, tj = t & 15, i0 = ti * 4, o0 = tj * 4;
    const float* src = (isK ? Kin : Qin) + ((size_t)h * NN + row0) * 64;

    for (int i = t; i < 4096; i += 256) {
        AT[(i & 63) * PDT + (i >> 6)] = src[i];
        WT[(i >> 6) * PDT + (i & 63)] = W1[(i & 63) * 64 + (i >> 6)];
    }
    __syncthreads();

    float out[16];
    gemmT(AT, WT, i0, o0, out);
    __syncthreads();
#pragma unroll
    for (int jj = 0; jj < 4; jj++) {
        const float bb = b1[o0 + jj];
        *(float4*)&BT[(o0 + jj) * PDT + i0] = make_float4(
            fmaxf(out[0 * 4 + jj] + bb, 0.f), fmaxf(out[1 * 4 + jj] + bb, 0.f),
            fmaxf(out[2 * 4 + jj] + bb, 0.f), fmaxf(out[3 * 4 + jj] + bb, 0.f));
    }
    for (int i = t; i < 4096; i += 256)
        WT[(i >> 6) * PDT + (i & 63)] = W2[(i & 63) * 64 + (i >> 6)];
    __syncthreads();
    gemmT(BT, WT, i0, o0, out);
    __syncthreads();
#pragma unroll
    for (int jj = 0; jj < 4; jj++) {
        const float bb = b2[o0 + jj];
        *(float4*)&AT[(o0 + jj) * PDT + i0] = make_float4(
            out[0 * 4 + jj] + bb, out[1 * 4 + jj] + bb,
            out[2 * 4 + jj] + bb, out[3 * 4 + jj] + bb);
    }
    for (int i = t; i < 4096; i += 256)
        WT[(i >> 6) * PDT + (i & 63)] = clusters[(size_t)h * 4096 + (i & 63) * 64 + (i >> 6)];
    __syncthreads();
    gemmT(AT, WT, i0, o0, out);
#pragma unroll
    for (int q = 0; q < 16; q++) out[q] = 1.f / (1.f + expf(-out[q]));

    if (isK) {
#pragma unroll
        for (int ii = 0; ii < 4; ii++)
            *(float4*)&g_KH[((size_t)h * NN + row0 + i0 + ii) * 64 + o0] =
                make_float4(out[ii * 4 + 0], out[ii * 4 + 1], out[ii * 4 + 2], out[ii * 4 + 3]);
    } else {
        __syncthreads();
#pragma unroll
        for (int jj = 0; jj < 4; jj++)
            *(float4*)&BT[(o0 + jj) * PDT + i0] = make_float4(
                out[0 * 4 + jj], out[1 * 4 + jj], out[2 * 4 + jj], out[3 * 4 + jj]);
        for (int i = t; i < 4096; i += 256)
            WT[(i >> 6) * PDT + (i & 63)] = g_S[(size_t)h * 4096 + i];
        __syncthreads();
        gemmT(BT, WT, i0, o0, out);
#pragma unroll
        for (int ii = 0; ii < 4; ii++)
            *(float4*)&g_T[((size_t)h * NN + row0 + i0 + ii) * 64 + o0] =
                make_float4(out[ii * 4 + 0], out[ii * 4 + 1], out[ii * 4 + 2], out[ii * 4 + 3]);
    }
}

// ============================================================
// Kernel C: fused attention, mma.sync tf32, 3-product split everywhere.
// 256 thr / 8 warps = 4 row-strips (16 rows) x 2 col-groups (32 cols).
// BM=64 rows per CTA; 64-col K-tiles. Independent-accumulator mma runs.
// ============================================================
__global__ void __launch_bounds__(256) k_attn(
    const float* __restrict__ Qg, const float* __restrict__ Kg,
    const float* __restrict__ Vg, const int* __restrict__ maskg,
    const float* __restrict__ ug, float* __restrict__ Xout) {
    extern __shared__ float sf[];
    uint32_t* su = (uint32_t*)sf;
    const int t = threadIdx.x, l = t & 31, w = t >> 5;
    const int lg = l >> 2, lt = l & 3;
    const int s4 = w & 3, cg = w >> 2;
    const int h = blockIdx.y, row0 = blockIdx.x * BM;

    // ---- prologue: A fragments. Warps 0-3: Q strips 0-3; warps 4-7: T strips 0-3 ----
    {
        const float* As = (w < 4 ? Qg : g_T) + ((size_t)h * NN + row0) * 64;
        const int bHI = (w < 4) ? F_QHI : F_THI;
        const int bLO = (w < 4) ? F_QLO : F_TLO;
        for (int ks = 0; ks < 8; ks++) {
#pragma unroll
            for (int i = 0; i < 4; i++) {
                const int row = 16 * s4 + lg + 8 * (i & 1);
                const int col = 8 * ks + lt + 4 * (i >> 1);
                const float v = As[row * 64 + col];
                const int fi = ((s4 * 8 + ks) * 32 + l) * 4 + i;
                su[bHI + fi] = tfhi(v);
                su[bLO + fi] = tflo(v);
            }
        }
    }

    float Co[4][4];
#pragma unroll
    for (int nt = 0; nt < 4; nt++)
#pragma unroll
        for (int q = 0; q < 4; q++) Co[nt][q] = 0.f;
    float Lp0 = 0.f, Lp1 = 0.f;
    unsigned cnt = 0;
    const int gr0 = row0 + 16 * s4 + lg, gr1 = gr0 + 8;
    const float* u0p = ug + ((size_t)h * NN + gr0) * NN;
    const float* u1p = ug + ((size_t)h * NN + gr1) * NN;

    for (int tile = 0; tile < NTILE; tile++) {
        const int c0 = tile * 64;
        __syncthreads();   // prev PV done reading E/V; prologue done (tile 0)
        {
            const float* ks_ = Kg + ((size_t)h * NN + c0) * 64;
            const float* kh_ = g_KH + ((size_t)h * NN + c0) * 64;
            const float* vs_ = Vg + ((size_t)h * NN + c0) * 64;
            for (int i = t; i < 4096; i += 256) {
                const int j = i >> 6, d = i & 63;
                const float kv = ks_[i], hv = kh_[i], vv = vs_[i];
                su[F_KHI  + j * 68 + d] = tfhi(kv);
                su[F_KLO  + j * 68 + d] = tflo(kv);
                su[F_KHHI + j * 68 + d] = tfhi(hv);
                su[F_KHLO + j * 68 + d] = tflo(hv);
                su[F_VHI  + j * 72 + d] = tfhi(vv);
                su[F_VLO  + j * 72 + d] = tflo(vv);
            }
            const int mv = (t < 64) ? (maskg[c0 + t] != 0) : 0;
            const unsigned bal = __ballot_sync(0xffffffffu, mv);
            if (t == 0)  su[F_CTRL + 0] = bal;
            if (t == 32) su[F_CTRL + 1] = bal;
        }
        __syncthreads();

        // ---- prefetch u (overlaps with mma loop) ----
        float2 ua[4], ub[4];
#pragma unroll
        for (int nt = 0; nt < 4; nt++) {
            const int jc = c0 + cg * 32 + nt * 8 + 2 * lt;
            ua[nt] = *(const float2*)&u0p[jc];
            ub[nt] = *(const float2*)&u1p[jc];
        }

        // ---- S = QK^T, EA = T Khat^T, both 3-split, ILP-ordered ----
        float Cs[4][4], Ce[4][4];
#pragma unroll
        for (int nt = 0; nt < 4; nt++)
#pragma unroll
            for (int q = 0; q < 4; q++) { Cs[nt][q] = 0.f; Ce[nt][q] = 0.f; }

        for (int ks = 0; ks < 8; ks++) {
            const int fb = ((s4 * 8 + ks) * 32 + l) * 4;
            const uint4 qh = *(const uint4*)&su[F_QHI + fb];
            const uint4 ql = *(const uint4*)&su[F_QLO + fb];
            const uint4 th = *(const uint4*)&su[F_THI + fb];
            const uint4 tl = *(const uint4*)&su[F_TLO + fb];
            uint32_t kb[4][2], kl[4][2], hb[4][2], hl[4][2];
            const int ksd = 8 * ks + lt;
#pragma unroll
            for (int nt = 0; nt < 4; nt++) {
                const int jb = (cg * 32 + nt * 8 + lg) * 68 + ksd;
                kb[nt][0] = su[F_KHI + jb];  kb[nt][1] = su[F_KHI + jb + 4];
                kl[nt][0] = su[F_KLO + jb];  kl[nt][1] = su[F_KLO + jb + 4];
                hb[nt][0] = su[F_KHHI + jb]; hb[nt][1] = su[F_KHHI + jb + 4];
                hl[nt][0] = su[F_KHLO + jb]; hl[nt][1] = su[F_KHLO + jb + 4];
            }
            // runs of 4 independent accumulators; same-acc reuse distance = 8
#pragma unroll
            for (int nt = 0; nt < 4; nt++) mma8(Cs[nt], qh.x, qh.y, qh.z, qh.w, kb[nt][0], kb[nt][1]);
#pragma unroll
            for (int nt = 0; nt < 4; nt++) mma8(Ce[nt], th.x, th.y, th.z, th.w, hb[nt][0], hb[nt][1]);
#pragma unroll
            for (int nt = 0; nt < 4; nt++) mma8(Cs[nt], qh.x, qh.y, qh.z, qh.w, kl[nt][0], kl[nt][1]);
#pragma unroll
            for (int nt = 0; nt < 4; nt++) mma8(Ce[nt], th.x, th.y, th.z, th.w, hl[nt][0], hl[nt][1]);
#pragma unroll
            for (int nt = 0; nt < 4; nt++) mma8(Cs[nt], ql.x, ql.y, ql.z, ql.w, kb[nt][0], kb[nt][1]);
#pragma unroll
            for (int nt = 0; nt < 4; nt++) mma8(Ce[nt], tl.x, tl.y, tl.z, tl.w, hb[nt][0], hb[nt][1]);
        }

        // ---- graph bit + exp (logits ~ N(0,1): no max shift needed) ----
        const u64 mall = (u64)su[F_CTRL + 0] | ((u64)su[F_CTRL + 1] << 32);
#pragma unroll
        for (int nt = 0; nt < 4; nt++) {
            const int jc = cg * 32 + nt * 8 + 2 * lt;
            const int mA = (int)((mall >> jc) & 1u), mB = (int)((mall >> (jc + 1)) & 1u);
            const unsigned g0 = (ua[nt].x < Ce[nt][0]) ? 1u : 0u;
            const unsigned g1 = (ua[nt].y < Ce[nt][1]) ? 1u : 0u;
            const unsigned g2 = (ub[nt].x < Ce[nt][2]) ? 1u : 0u;
            const unsigned g3 = (ub[nt].y < Ce[nt][3]) ? 1u : 0u;
            cnt += g0 + g1 + g2 + g3;
            const float e0 = (g0 && mA) ? __expf(Cs[nt][0] * 0.125f) : 0.f;
            const float e1 = (g1 && mB) ? __expf(Cs[nt][1] * 0.125f) : 0.f;
            const float e2 = (g2 && mA) ? __expf(Cs[nt][2] * 0.125f) : 0.f;
            const float e3 = (g3 && mB) ? __expf(Cs[nt][3] * 0.125f) : 0.f;
            Lp0 += e0 + e1; Lp1 += e2 + e3;
            Cs[nt][0] = e0; Cs[nt][1] = e1; Cs[nt][2] = e2; Cs[nt][3] = e3;
        }
        __syncthreads();   // all warps done reading K/KH before E aliases them

        // ---- spill E hi/lo (tf32 split) ----
#pragma unroll
        for (int nt = 0; nt < 4; nt++) {
            const int col = cg * 32 + nt * 8 + 2 * lt;
            const int r0 = 16 * s4 + lg, r1 = r0 + 8;
            *(uint2*)&su[F_EHI + r0 * 68 + col] = make_uint2(tfhi(Cs[nt][0]), tfhi(Cs[nt][1]));
            *(uint2*)&su[F_ELO + r0 * 68 + col] = make_uint2(tflo(Cs[nt][0]), tflo(Cs[nt][1]));
            *(uint2*)&su[F_EHI + r1 * 68 + col] = make_uint2(tfhi(Cs[nt][2]), tfhi(Cs[nt][3]));
            *(uint2*)&su[F_ELO + r1 * 68 + col] = make_uint2(tflo(Cs[nt][2]), tflo(Cs[nt][3]));
        }
        __syncthreads();

        // ---- PV: O += E @ V, 3-split ----
        for (int ks = 0; ks < 8; ks++) {
            const int ad = (16 * s4 + lg) * 68 + 8 * ks + lt;
            const uint32_t eh0 = su[F_EHI + ad],     eh1 = su[F_EHI + ad + 8 * 68];
            const uint32_t eh2 = su[F_EHI + ad + 4], eh3 = su[F_EHI + ad + 8 * 68 + 4];
            const uint32_t el0 = su[F_ELO + ad],     el1 = su[F_ELO + ad + 8 * 68];
            const uint32_t el2 = su[F_ELO + ad + 4], el3 = su[F_ELO + ad + 8 * 68 + 4];
            uint32_t vh[4][2], vl[4][2];
#pragma unroll
            for (int nt = 0; nt < 4; nt++) {
                const int vb = (8 * ks + lt) * 72 + cg * 32 + nt * 8 + lg;
                vh[nt][0] = su[F_VHI + vb]; vh[nt][1] = su[F_VHI + vb + 4 * 72];
                vl[nt][0] = su[F_VLO + vb]; vl[nt][1] = su[F_VLO + vb + 4 * 72];
            }
#pragma unroll
            for (int nt = 0; nt < 4; nt++) mma8(Co[nt], eh0, eh1, eh2, eh3, vh[nt][0], vh[nt][1]);
#pragma unroll
            for (int nt = 0; nt < 4; nt++) mma8(Co[nt], eh0, eh1, eh2, eh3, vl[nt][0], vl[nt][1]);
#pragma unroll
            for (int nt = 0; nt < 4; nt++) mma8(Co[nt], el0, el1, el2, el3, vh[nt][0], vh[nt][1]);
        }
    }

    // ---- epilogue: L reduce (quad + cross-col-group), X = O / L ----
    Lp0 += __shfl_xor_sync(0xffffffffu, Lp0, 1);
    Lp0 += __shfl_xor_sync(0xffffffffu, Lp0, 2);
    Lp1 += __shfl_xor_sync(0xffffffffu, Lp1, 1);
    Lp1 += __shfl_xor_sync(0xffffffffu, Lp1, 2);
    __syncthreads();   // last PV reads of E done before L exchange reuses F_KLO
    if (lt == 0) {
        sf[F_LX + (s4 * 2 + cg) * 16 + lg] = Lp0;
        sf[F_LX + (s4 * 2 + cg) * 16 + lg + 8] = Lp1;
    }
    __syncthreads();
    const float L0 = sf[F_LX + (s4 * 2 + 0) * 16 + lg] + sf[F_LX + (s4 * 2 + 1) * 16 + lg];
    const float L1 = sf[F_LX + (s4 * 2 + 0) * 16 + lg + 8] + sf[F_LX + (s4 * 2 + 1) * 16 + lg + 8];
    const float r0 = (L0 > 0.f) ? (1.f / L0) : 0.f;
    const float r1 = (L1 > 0.f) ? (1.f / L1) : 0.f;
    float* X0 = Xout + ((size_t)h * NN + gr0) * 64;
    float* X1 = Xout + ((size_t)h * NN + gr1) * 64;
#pragma unroll
    for (int nt = 0; nt < 4; nt++) {
        const int jc = cg * 32 + nt * 8 + 2 * lt;
        *(float2*)&X0[jc] = make_float2(Co[nt][0] * r0, Co[nt][1] * r0);
        *(float2*)&X1[jc] = make_float2(Co[nt][2] * r1, Co[nt][3] * r1);
    }

    // ---- sparsity popcount ----
#pragma unroll
    for (int off = 16; off > 0; off >>= 1) cnt += __shfl_xor_sync(0xffffffffu, cnt, off);
    if (l == 0) su[F_CTRL + 2 + w] = cnt;
    __syncthreads();
    if (t == 0) {
        unsigned tot = 0;
#pragma unroll
        for (int i = 0; i < 8; i++) tot += su[F_CTRL + 2 + i];
        atomicAdd(&g_cnt[h], tot);
    }
}

// ============================================================
__global__ void k_spars(float* __restrict__ out) {
    const int h = threadIdx.x;
    if (h < NH) out[h] = (float)g_cnt[h] * (1.0f / ((float)NN * (float)NN));
}

// ============================================================
extern "C" void kernel_launch(void* const* d_in, const int* in_sizes, int n_in,
                              void* d_out, int out_size) {
    (void)in_sizes; (void)n_in;
    const float* Q        = (const float*)d_in[0];
    const float* K        = (const float*)d_in[1];
    const float* V        = (const float*)d_in[2];
    const int*   mask     = (const int*)d_in[3];
    const float* u        = (const float*)d_in[4];
    const float* clusters = (const float*)d_in[5];
    const float* W1       = (const float*)d_in[6];
    const float* b1       = (const float*)d_in[7];
    const float* W2       = (const float*)d_in[8];
    const float* b2       = (const float*)d_in[9];
    float* X = (float*)d_out;
    float* spars = X + (out_size - NH);

    const int SMB = 3 * 64 * PDT * 4;
    cudaFuncSetAttribute(k_projhat, cudaFuncAttributeMaxDynamicSharedMemorySize, SMB);
    cudaFuncSetAttribute(k_attn, cudaFuncAttributeMaxDynamicSharedMemorySize, SMEM_ATTN);

    k_clusterS<<<NH, 256>>>(clusters);
    k_projhat<<<dim3(NN / 64, NH, 2), 256, SMB>>>(Q, K, clusters, W1, b1, W2, b2);
    k_attn<<<dim3(NN / BM, NH), 256, SMEM_ATTN>>>(Q, K, V, mask, u, X);
    k_spars<<<1, NH>>>(spars);
}

// round 9
// speedup vs baseline: 1.5576x; 1.5576x over previous
#include <cuda_runtime.h>
#include <cuda_fp16.h>
#include <cstdint>
#include <math.h>

#define NH 8
#define NN 2048
#define BM 128
#define NTILE 32
#define PDT 68

typedef unsigned long long u64;

// ---------------- smem word-offsets for k_attn ----------------
#define F_QHI  0          /* 8w x 4ks x 32l x 4 = 4096 */
#define F_QLO  4096
#define F_THI  8192
#define F_TLO  12288
#define F_KHI  16384      /* 64 rows x 36 = 2304 */
#define F_KLO  18688
#define F_HHI  20992
#define F_HLO  23296
#define F_VHI  25600      /* 32 jw x 68 = 2176 */
#define F_VLO  27776
#define F_CTRL 29952      /* [0,1]=mask ballot, [2..9]=warp counts */
#define SMEM_ATTN ((29952 + 16) * 4)   /* 119,872 B */

// ---------------- helpers ----------------
// split-pack: two fp32 -> fp16 hi-pair + fp16 lo-pair (residuals)
__device__ __forceinline__ void sp2(float xe, float xo, uint32_t& hi, uint32_t& lo) {
    const __half he = __float2half_rn(xe), ho = __float2half_rn(xo);
    const float re = xe - __half2float(he), ro = xo - __half2float(ho);
    const __half2 H = __halves2half2(he, ho);
    const __half2 L = __halves2half2(__float2half_rn(re), __float2half_rn(ro));
    hi = *(const uint32_t*)&H;
    lo = *(const uint32_t*)&L;
}
__device__ __forceinline__ void mma16(float c[4], uint32_t a0, uint32_t a1, uint32_t a2, uint32_t a3,
                                      uint32_t b0, uint32_t b1) {
    asm volatile(
        "mma.sync.aligned.m16n8k16.row.col.f32.f16.f16.f32 "
        "{%0,%1,%2,%3},{%4,%5,%6,%7},{%8,%9},{%0,%1,%2,%3};"
        : "+f"(c[0]), "+f"(c[1]), "+f"(c[2]), "+f"(c[3])
        : "r"(a0), "r"(a1), "r"(a2), "r"(a3), "r"(b0), "r"(b1));
}

// -------- device scratch --------
__device__ float g_S[NH * 64 * 64];
__device__ float g_T[NH * NN * 64];
__device__ float g_KH[NH * NN * 64];
__device__ unsigned int g_cnt[NH];

// ============================================================
// Kernel A: S = softmax over flattened k*k of clusters @ clusters^T
// ============================================================
__global__ void k_clusterS(const float* __restrict__ clusters) {
    __shared__ float cl[64 * 64];
    __shared__ float ds[64 * 64];
    __shared__ float red[256];
    const int h = blockIdx.x, t = threadIdx.x;
    for (int i = t; i < 4096; i += 256) cl[i] = clusters[(size_t)h * 4096 + i];
    __syncthreads();
    float lmax = -1e30f;
    for (int i = t; i < 4096; i += 256) {
        const int kk = i >> 6, jj = i & 63;
        float s = 0.f;
#pragma unroll 16
        for (int d = 0; d < 64; d++) s += cl[kk * 64 + d] * cl[jj * 64 + d];
        ds[i] = s;
        lmax = fmaxf(lmax, s);
    }
    red[t] = lmax;
    __syncthreads();
    for (int o = 128; o > 0; o >>= 1) { if (t < o) red[t] = fmaxf(red[t], red[t + o]); __syncthreads(); }
    const float mx = red[0];
    __syncthreads();
    float lsum = 0.f;
    for (int i = t; i < 4096; i += 256) { const float e = expf(ds[i] - mx); ds[i] = e; lsum += e; }
    red[t] = lsum;
    __syncthreads();
    for (int o = 128; o > 0; o >>= 1) { if (t < o) red[t] += red[t + o]; __syncthreads(); }
    const float inv = 1.f / red[0];
    for (int i = t; i < 4096; i += 256) g_S[(size_t)h * 4096 + i] = ds[i] * inv;
    if (t == 0) g_cnt[h] = 0u;
}

// ============================================================
// k-major 64^3 SIMT GEMM helper for k_projhat (exact fp32)
// ============================================================
__device__ __forceinline__ void gemmT(const float* __restrict__ AT, const float* __restrict__ WT,
                                      int i0, int o0, float out[16]) {
    float acc[16];
#pragma unroll
    for (int q = 0; q < 16; q++) acc[q] = 0.f;
#pragma unroll 8
    for (int k = 0; k < 64; k++) {
        const float4 a = *(const float4*)&AT[k * PDT + i0];
        const float4 w = *(const float4*)&WT[k * PDT + o0];
        const float av[4] = {a.x, a.y, a.z, a.w};
        const float wv[4] = {w.x, w.y, w.z, w.w};
#pragma unroll
        for (int ii = 0; ii < 4; ii++)
#pragma unroll
            for (int jj = 0; jj < 4; jj++) acc[ii * 4 + jj] += av[ii] * wv[jj];
    }
#pragma unroll
    for (int q = 0; q < 16; q++) out[q] = acc[q];
}

__global__ void __launch_bounds__(256) k_projhat(
    const float* __restrict__ Qin, const float* __restrict__ Kin,
    const float* __restrict__ clusters, const float* __restrict__ W1,
    const float* __restrict__ b1, const float* __restrict__ W2,
    const float* __restrict__ b2) {
    extern __shared__ float smb[];
    float* AT = smb;
    float* BT = smb + 64 * PDT;
    float* WT = smb + 2 * 64 * PDT;
    const int t = threadIdx.x;
    const int h = blockIdx.y;
    const int row0 = blockIdx.x * 64;
    const int isK = blockIdx.z;
    const int ti = t >> 4, tj = t & 15, i0 = ti * 4, o0 = tj * 4;
    const float* src = (isK ? Kin : Qin) + ((size_t)h * NN + row0) * 64;

    for (int i = t; i < 4096; i += 256) {
        AT[(i & 63) * PDT + (i >> 6)] = src[i];
        WT[(i >> 6) * PDT + (i & 63)] = W1[(i & 63) * 64 + (i >> 6)];
    }
    __syncthreads();

    float out[16];
    gemmT(AT, WT, i0, o0, out);
    __syncthreads();
#pragma unroll
    for (int jj = 0; jj < 4; jj++) {
        const float bb = b1[o0 + jj];
        *(float4*)&BT[(o0 + jj) * PDT + i0] = make_float4(
            fmaxf(out[0 * 4 + jj] + bb, 0.f), fmaxf(out[1 * 4 + jj] + bb, 0.f),
            fmaxf(out[2 * 4 + jj] + bb, 0.f), fmaxf(out[3 * 4 + jj] + bb, 0.f));
    }
    for (int i = t; i < 4096; i += 256)
        WT[(i >> 6) * PDT + (i & 63)] = W2[(i & 63) * 64 + (i >> 6)];
    __syncthreads();
    gemmT(BT, WT, i0, o0, out);
    __syncthreads();
#pragma unroll
    for (int jj = 0; jj < 4; jj++) {
        const float bb = b2[o0 + jj];
        *(float4*)&AT[(o0 + jj) * PDT + i0] = make_float4(
            out[0 * 4 + jj] + bb, out[1 * 4 + jj] + bb,
            out[2 * 4 + jj] + bb, out[3 * 4 + jj] + bb);
    }
    for (int i = t; i < 4096; i += 256)
        WT[(i >> 6) * PDT + (i & 63)] = clusters[(size_t)h * 4096 + (i & 63) * 64 + (i >> 6)];
    __syncthreads();
    gemmT(AT, WT, i0, o0, out);
#pragma unroll
    for (int q = 0; q < 16; q++) out[q] = 1.f / (1.f + expf(-out[q]));

    if (isK) {
#pragma unroll
        for (int ii = 0; ii < 4; ii++)
            *(float4*)&g_KH[((size_t)h * NN + row0 + i0 + ii) * 64 + o0] =
                make_float4(out[ii * 4 + 0], out[ii * 4 + 1], out[ii * 4 + 2], out[ii * 4 + 3]);
    } else {
        __syncthreads();
#pragma unroll
        for (int jj = 0; jj < 4; jj++)
            *(float4*)&BT[(o0 + jj) * PDT + i0] = make_float4(
                out[0 * 4 + jj], out[1 * 4 + jj], out[2 * 4 + jj], out[3 * 4 + jj]);
        for (int i = t; i < 4096; i += 256)
            WT[(i >> 6) * PDT + (i & 63)] = g_S[(size_t)h * 4096 + i];
        __syncthreads();
        gemmT(BT, WT, i0, o0, out);
#pragma unroll
        for (int ii = 0; ii < 4; ii++)
            *(float4*)&g_T[((size_t)h * NN + row0 + i0 + ii) * 64 + o0] =
                make_float4(out[ii * 4 + 0], out[ii * 4 + 1], out[ii * 4 + 2], out[ii * 4 + 3]);
    }
}

// ============================================================
// Kernel C: fused attention, mma.sync fp16 m16n8k16, hi/lo splits.
// BM=128, 8 warps x 16-row strips, each warp covers all 64 cols.
// E stays in registers (accum layout == A-frag layout for fp16 k16).
// ============================================================
__global__ void __launch_bounds__(256) k_attn(
    const float* __restrict__ Qg, const float* __restrict__ Kg,
    const float* __restrict__ Vg, const int* __restrict__ maskg,
    const float* __restrict__ ug, float* __restrict__ Xout) {
    extern __shared__ float sf[];
    uint32_t* su = (uint32_t*)sf;
    const int t = threadIdx.x, l = t & 31, w = t >> 5;
    const int lg = l >> 2, lt = l & 3;
    const int h = blockIdx.y, row0 = blockIdx.x * BM;

    // ---- prologue: Q and T A-fragments (fp16 hi/lo), fragment-major ----
    {
        const float* Qs = Qg + ((size_t)h * NN + row0) * 64;
        const float* Ts = g_T + ((size_t)h * NN + row0) * 64;
        for (int ks = 0; ks < 4; ks++) {
#pragma unroll
            for (int i = 0; i < 4; i++) {
                const int row = 16 * w + lg + 8 * (i & 1);
                const int col = 16 * ks + 2 * lt + 8 * (i >> 1);
                const int fi = ((w * 4 + ks) * 32 + l) * 4 + i;
                const float2 q = *(const float2*)&Qs[row * 64 + col];
                sp2(q.x, q.y, su[F_QHI + fi], su[F_QLO + fi]);
                const float2 tv = *(const float2*)&Ts[row * 64 + col];
                sp2(tv.x, tv.y, su[F_THI + fi], su[F_TLO + fi]);
            }
        }
    }

    float Co[8][4];
#pragma unroll
    for (int nt = 0; nt < 8; nt++)
#pragma unroll
        for (int q = 0; q < 4; q++) Co[nt][q] = 0.f;
    float Lp0 = 0.f, Lp1 = 0.f;
    unsigned cnt = 0;
    const int gr0 = row0 + 16 * w + lg, gr1 = gr0 + 8;
    const float* u0p = ug + ((size_t)h * NN + gr0) * NN;
    const float* u1p = ug + ((size_t)h * NN + gr1) * NN;

    for (int tile = 0; tile < NTILE; tile++) {
        const int c0 = tile * 64;
        __syncthreads();   // prev tile's mma reads done; prologue done (tile 0)
        {
            const float* ks_ = Kg + ((size_t)h * NN + c0) * 64;
            const float* kh_ = g_KH + ((size_t)h * NN + c0) * 64;
            const float* vs_ = Vg + ((size_t)h * NN + c0) * 64;
            // K / KH: word (j, kw), d-pairs packed; stride 36 (conflict-free STS+LDS)
            for (int i = t; i < 2048; i += 256) {
                const int j = i >> 5, kw = i & 31;
                const float2 kv = *(const float2*)&ks_[j * 64 + 2 * kw];
                sp2(kv.x, kv.y, su[F_KHI + j * 36 + kw], su[F_KLO + j * 36 + kw]);
                const float2 hv = *(const float2*)&kh_[j * 64 + 2 * kw];
                sp2(hv.x, hv.y, su[F_HHI + j * 36 + kw], su[F_HLO + j * 36 + kw]);
            }
            // V: word (jw, d), j-pairs packed; jw-major stride 68 (conflict-free)
            for (int i = t; i < 2048; i += 256) {
                const int jw = i >> 6, d = i & 63;
                const float v0 = vs_[(2 * jw) * 64 + d];
                const float v1 = vs_[(2 * jw + 1) * 64 + d];
                sp2(v0, v1, su[F_VHI + jw * 68 + d], su[F_VLO + jw * 68 + d]);
            }
            const int mv = (t < 64) ? (maskg[c0 + t] != 0) : 0;
            const unsigned bal = __ballot_sync(0xffffffffu, mv);
            if (t == 0)  su[F_CTRL + 0] = bal;
            if (t == 32) su[F_CTRL + 1] = bal;
        }
        __syncthreads();

        // ---- prefetch u ----
        float2 ua[8], ub[8];
#pragma unroll
        for (int nt = 0; nt < 8; nt++) {
            const int jc = c0 + nt * 8 + 2 * lt;
            ua[nt] = *(const float2*)&u0p[jc];
            ub[nt] = *(const float2*)&u1p[jc];
        }

        // ---- S = QK^T (3 products), EA = T Khat^T (4 products) ----
        float Cs[8][4], Ce[8][4];
#pragma unroll
        for (int nt = 0; nt < 8; nt++)
#pragma unroll
            for (int q = 0; q < 4; q++) { Cs[nt][q] = 0.f; Ce[nt][q] = 0.f; }

        for (int ks = 0; ks < 4; ks++) {
            const int fb = ((w * 4 + ks) * 32 + l) * 4;
            const uint4 qh = *(const uint4*)&su[F_QHI + fb];
            const uint4 ql = *(const uint4*)&su[F_QLO + fb];
            const uint4 th = *(const uint4*)&su[F_THI + fb];
            const uint4 tl = *(const uint4*)&su[F_TLO + fb];
#pragma unroll
            for (int hf = 0; hf < 2; hf++) {
                uint32_t kb[4][2], kl[4][2], hb[4][2], hl[4][2];
#pragma unroll
                for (int n = 0; n < 4; n++) {
                    const int jb = ((hf * 4 + n) * 8 + lg) * 36 + 8 * ks + lt;
                    kb[n][0] = su[F_KHI + jb]; kb[n][1] = su[F_KHI + jb + 4];
                    kl[n][0] = su[F_KLO + jb]; kl[n][1] = su[F_KLO + jb + 4];
                    hb[n][0] = su[F_HHI + jb]; hb[n][1] = su[F_HHI + jb + 4];
                    hl[n][0] = su[F_HLO + jb]; hl[n][1] = su[F_HLO + jb + 4];
                }
                float* CsH = &Cs[hf * 4][0];
                float* CeH = &Ce[hf * 4][0];
#pragma unroll
                for (int n = 0; n < 4; n++) mma16(&CsH[n * 4], qh.x, qh.y, qh.z, qh.w, kb[n][0], kb[n][1]);
#pragma unroll
                for (int n = 0; n < 4; n++) mma16(&CeH[n * 4], th.x, th.y, th.z, th.w, hb[n][0], hb[n][1]);
#pragma unroll
                for (int n = 0; n < 4; n++) mma16(&CsH[n * 4], qh.x, qh.y, qh.z, qh.w, kl[n][0], kl[n][1]);
#pragma unroll
                for (int n = 0; n < 4; n++) mma16(&CeH[n * 4], th.x, th.y, th.z, th.w, hl[n][0], hl[n][1]);
#pragma unroll
                for (int n = 0; n < 4; n++) mma16(&CsH[n * 4], ql.x, ql.y, ql.z, ql.w, kb[n][0], kb[n][1]);
#pragma unroll
                for (int n = 0; n < 4; n++) mma16(&CeH[n * 4], tl.x, tl.y, tl.z, tl.w, hb[n][0], hb[n][1]);
#pragma unroll
                for (int n = 0; n < 4; n++) mma16(&CeH[n * 4], tl.x, tl.y, tl.z, tl.w, hl[n][0], hl[n][1]);
            }
        }

        // ---- graph bit + exp; pack E into fp16 hi/lo A-frag pairs (in regs) ----
        const u64 mall = (u64)su[F_CTRL + 0] | ((u64)su[F_CTRL + 1] << 32);
        uint32_t ehi[8][2], elo[8][2];
#pragma unroll
        for (int nt = 0; nt < 8; nt++) {
            const int jc = nt * 8 + 2 * lt;
            const int mA = (int)((mall >> jc) & 1u), mB = (int)((mall >> (jc + 1)) & 1u);
            const unsigned g0 = (ua[nt].x < Ce[nt][0]) ? 1u : 0u;
            const unsigned g1 = (ua[nt].y < Ce[nt][1]) ? 1u : 0u;
            const unsigned g2 = (ub[nt].x < Ce[nt][2]) ? 1u : 0u;
            const unsigned g3 = (ub[nt].y < Ce[nt][3]) ? 1u : 0u;
            cnt += g0 + g1 + g2 + g3;
            const float e0 = (g0 && mA) ? __expf(Cs[nt][0] * 0.125f) : 0.f;
            const float e1 = (g1 && mB) ? __expf(Cs[nt][1] * 0.125f) : 0.f;
            const float e2 = (g2 && mA) ? __expf(Cs[nt][2] * 0.125f) : 0.f;
            const float e3 = (g3 && mB) ? __expf(Cs[nt][3] * 0.125f) : 0.f;
            Lp0 += e0 + e1;
            Lp1 += e2 + e3;
            sp2(e0, e1, ehi[nt][0], elo[nt][0]);   // rows lg
            sp2(e2, e3, ehi[nt][1], elo[nt][1]);   // rows lg+8
        }

        // ---- PV: O += E @ V (3 products), A-frags straight from registers ----
        for (int ks = 0; ks < 4; ks++) {
            const uint32_t ah0 = ehi[2 * ks][0], ah1 = ehi[2 * ks][1];
            const uint32_t ah2 = ehi[2 * ks + 1][0], ah3 = ehi[2 * ks + 1][1];
            const uint32_t al0 = elo[2 * ks][0], al1 = elo[2 * ks][1];
            const uint32_t al2 = elo[2 * ks + 1][0], al3 = elo[2 * ks + 1][1];
#pragma unroll
            for (int hf = 0; hf < 2; hf++) {
                uint32_t vh[4][2], vl[4][2];
#pragma unroll
                for (int n = 0; n < 4; n++) {
                    const int vb = (8 * ks + lt) * 68 + (hf * 4 + n) * 8 + lg;
                    vh[n][0] = su[F_VHI + vb]; vh[n][1] = su[F_VHI + vb + 4 * 68];
                    vl[n][0] = su[F_VLO + vb]; vl[n][1] = su[F_VLO + vb + 4 * 68];
                }
                float* CoH = &Co[hf * 4][0];
#pragma unroll
                for (int n = 0; n < 4; n++) mma16(&CoH[n * 4], ah0, ah1, ah2, ah3, vh[n][0], vh[n][1]);
#pragma unroll
                for (int n = 0; n < 4; n++) mma16(&CoH[n * 4], ah0, ah1, ah2, ah3, vl[n][0], vl[n][1]);
#pragma unroll
                for (int n = 0; n < 4; n++) mma16(&CoH[n * 4], al0, al1, al2, al3, vh[n][0], vh[n][1]);
            }
        }
    }

    // ---- epilogue: L reduce over quad lanes, write X = O / L ----
    Lp0 += __shfl_xor_sync(0xffffffffu, Lp0, 1);
    Lp0 += __shfl_xor_sync(0xffffffffu, Lp0, 2);
    Lp1 += __shfl_xor_sync(0xffffffffu, Lp1, 1);
    Lp1 += __shfl_xor_sync(0xffffffffu, Lp1, 2);
    const float r0 = (Lp0 > 0.f) ? (1.f / Lp0) : 0.f;
    const float r1 = (Lp1 > 0.f) ? (1.f / Lp1) : 0.f;
    float* X0 = Xout + ((size_t)h * NN + gr0) * 64;
    float* X1 = Xout + ((size_t)h * NN + gr1) * 64;
#pragma unroll
    for (int nt = 0; nt < 8; nt++) {
        const int jc = nt * 8 + 2 * lt;
        *(float2*)&X0[jc] = make_float2(Co[nt][0] * r0, Co[nt][1] * r0);
        *(float2*)&X1[jc] = make_float2(Co[nt][2] * r1, Co[nt][3] * r1);
    }

    // ---- sparsity popcount ----
#pragma unroll
    for (int off = 16; off > 0; off >>= 1) cnt += __shfl_xor_sync(0xffffffffu, cnt, off);
    __syncthreads();
    if (l == 0) su[F_CTRL + 2 + w] = cnt;
    __syncthreads();
    if (t == 0) {
        unsigned tot = 0;
#pragma unroll
        for (int i = 0; i < 8; i++) tot += su[F_CTRL + 2 + i];
        atomicAdd(&g_cnt[h], tot);
    }
}

// ============================================================
__global__ void k_spars(float* __restrict__ out) {
    const int h = threadIdx.x;
    if (h < NH) out[h] = (float)g_cnt[h] * (1.0f / ((float)NN * (float)NN));
}

// ============================================================
extern "C" void kernel_launch(void* const* d_in, const int* in_sizes, int n_in,
                              void* d_out, int out_size) {
    (void)in_sizes; (void)n_in;
    const float* Q        = (const float*)d_in[0];
    const float* K        = (const float*)d_in[1];
    const float* V        = (const float*)d_in[2];
    const int*   mask     = (const int*)d_in[3];
    const float* u        = (const float*)d_in[4];
    const float* clusters = (const float*)d_in[5];
    const float* W1       = (const float*)d_in[6];
    const float* b1       = (const float*)d_in[7];
    const float* W2       = (const float*)d_in[8];
    const float* b2       = (const float*)d_in[9];
    float* X = (float*)d_out;
    float* spars = X + (out_size - NH);

    const int SMB = 3 * 64 * PDT * 4;
    cudaFuncSetAttribute(k_projhat, cudaFuncAttributeMaxDynamicSharedMemorySize, SMB);
    cudaFuncSetAttribute(k_attn, cudaFuncAttributeMaxDynamicSharedMemorySize, SMEM_ATTN);

    k_clusterS<<<NH, 256>>>(clusters);
    k_projhat<<<dim3(NN / 64, NH, 2), 256, SMB>>>(Q, K, clusters, W1, b1, W2, b2);
    k_attn<<<dim3(NN / BM, NH), 256, SMEM_ATTN>>>(Q, K, V, mask, u, X);
    k_spars<<<1, NH>>>(spars);
}

// round 12
// speedup vs baseline: 1.9830x; 1.2731x over previous
#include <cuda_runtime.h>
#include <cuda_fp16.h>
#include <cstdint>
#include <math.h>

#define NH 8
#define NN 2048
#define BM 128
#define NTILE 32
#define PDT 68

typedef unsigned long long u64;

// ---------------- k_attn smem word-offsets ----------------
#define F_QHI  0          /* A-frags: 8w x 4ks x 32l x 4 = 4096 words each */
#define F_QLO  4096
#define F_THI  8192
#define F_TLO  12288
// per-buffer word offsets (buffer size 13568 words)
#define O_KHI  0          /* 64 x 36 = 2304 */
#define O_KLO  2304
#define O_HHI  4608
#define O_HLO  6912
#define O_VHI  9216       /* 32 x 68 = 2176 */
#define O_VLO  11392
#define BUFSZ  13568
#define BUF0   16384
#define BUF1   29952
#define O_MSK  43520      /* 64 ballot words for the whole mask */
#define O_CNT  43584      /* 8 warp popcounts */
#define SMEM_ATTN ((43592) * 4)   /* 174,368 B */

// ---------------- helpers ----------------
// split-pack: two fp32 -> fp16 hi-pair + fp16 lo-pair (residuals)
__device__ __forceinline__ void sp2(float xe, float xo, uint32_t& hi, uint32_t& lo) {
    const __half he = __float2half_rn(xe), ho = __float2half_rn(xo);
    const float re = xe - __half2float(he), ro = xo - __half2float(ho);
    const __half2 H = __halves2half2(he, ho);
    const __half2 L = __halves2half2(__float2half_rn(re), __float2half_rn(ro));
    hi = *(const uint32_t*)&H;
    lo = *(const uint32_t*)&L;
}
__device__ __forceinline__ void mma16(float c[4], uint32_t a0, uint32_t a1, uint32_t a2, uint32_t a3,
                                      uint32_t b0, uint32_t b1) {
    asm volatile(
        "mma.sync.aligned.m16n8k16.row.col.f32.f16.f16.f32 "
        "{%0,%1,%2,%3},{%4,%5,%6,%7},{%8,%9},{%0,%1,%2,%3};"
        : "+f"(c[0]), "+f"(c[1]), "+f"(c[2]), "+f"(c[3])
        : "r"(a0), "r"(a1), "r"(a2), "r"(a3), "r"(b0), "r"(b1));
}
__device__ __forceinline__ void cp16(uint32_t dst_smem, const void* src) {
    asm volatile("cp.async.cg.shared.global [%0], [%1], 16;" :: "r"(dst_smem), "l"(src));
}
#define CP_COMMIT() asm volatile("cp.async.commit_group;" ::: "memory")
#define CP_WAIT0()  asm volatile("cp.async.wait_group 0;" ::: "memory")

// -------- device scratch --------
__device__ float g_S[NH * 64 * 64];
__device__ float g_T[NH * NN * 64];
__device__ uint32_t g_Khi[NH * NN * 32];
__device__ uint32_t g_Klo[NH * NN * 32];
__device__ uint32_t g_Hhi[NH * NN * 32];
__device__ uint32_t g_Hlo[NH * NN * 32];
__device__ uint32_t g_Vhi[NH * (NN / 2) * 64];
__device__ uint32_t g_Vlo[NH * (NN / 2) * 64];
__device__ unsigned int g_cnt[NH];

// ============================================================
// Kernel A: S = softmax over flattened k*k of clusters @ clusters^T
// ============================================================
__global__ void k_clusterS(const float* __restrict__ clusters) {
    __shared__ float cl[64 * 64];
    __shared__ float ds[64 * 64];
    __shared__ float red[256];
    const int h = blockIdx.x, t = threadIdx.x;
    for (int i = t; i < 4096; i += 256) cl[i] = clusters[(size_t)h * 4096 + i];
    __syncthreads();
    float lmax = -1e30f;
    for (int i = t; i < 4096; i += 256) {
        const int kk = i >> 6, jj = i & 63;
        float s = 0.f;
#pragma unroll 16
        for (int d = 0; d < 64; d++) s += cl[kk * 64 + d] * cl[jj * 64 + d];
        ds[i] = s;
        lmax = fmaxf(lmax, s);
    }
    red[t] = lmax;
    __syncthreads();
    for (int o = 128; o > 0; o >>= 1) { if (t < o) red[t] = fmaxf(red[t], red[t + o]); __syncthreads(); }
    const float mx = red[0];
    __syncthreads();
    float lsum = 0.f;
    for (int i = t; i < 4096; i += 256) { const float e = expf(ds[i] - mx); ds[i] = e; lsum += e; }
    red[t] = lsum;
    __syncthreads();
    for (int o = 128; o > 0; o >>= 1) { if (t < o) red[t] += red[t + o]; __syncthreads(); }
    const float inv = 1.f / red[0];
    for (int i = t; i < 4096; i += 256) g_S[(size_t)h * 4096 + i] = ds[i] * inv;
    if (t == 0) g_cnt[h] = 0u;
}

// ============================================================
// Kernel P: pack K and V inputs into fp16 hi/lo word arrays.
// ============================================================
__global__ void __launch_bounds__(256) k_prep(const float* __restrict__ K,
                                              const float* __restrict__ V) {
    const int idx = blockIdx.x * 256 + threadIdx.x;   // 0 .. 524287
    const int h = idx >> 16;
    const int rem = idx & 0xffff;
    {
        const int j = rem >> 5, kw = rem & 31;
        const float2 kv = *(const float2*)&K[((size_t)h * NN + j) * 64 + 2 * kw];
        uint32_t hi, lo;
        sp2(kv.x, kv.y, hi, lo);
        g_Khi[idx] = hi;
        g_Klo[idx] = lo;
    }
    {
        const int jw = rem >> 6, d = rem & 63;
        const float v0 = V[((size_t)h * NN + 2 * jw) * 64 + d];
        const float v1 = V[((size_t)h * NN + 2 * jw + 1) * 64 + d];
        uint32_t hi, lo;
        sp2(v0, v1, hi, lo);
        g_Vhi[idx] = hi;
        g_Vlo[idx] = lo;
    }
}

// ============================================================
// k-major 64^3 SIMT GEMM helper for k_projhat (exact fp32)
// ============================================================
__device__ __forceinline__ void gemmT(const float* __restrict__ AT, const float* __restrict__ WT,
                                      int i0, int o0, float out[16]) {
    float acc[16];
#pragma unroll
    for (int q = 0; q < 16; q++) acc[q] = 0.f;
#pragma unroll 8
    for (int k = 0; k < 64; k++) {
        const float4 a = *(const float4*)&AT[k * PDT + i0];
        const float4 w = *(const float4*)&WT[k * PDT + o0];
        const float av[4] = {a.x, a.y, a.z, a.w};
        const float wv[4] = {w.x, w.y, w.z, w.w};
#pragma unroll
        for (int ii = 0; ii < 4; ii++)
#pragma unroll
            for (int jj = 0; jj < 4; jj++) acc[ii * 4 + jj] += av[ii] * wv[jj];
    }
#pragma unroll
    for (int q = 0; q < 16; q++) out[q] = acc[q];
}

__global__ void __launch_bounds__(256) k_projhat(
    const float* __restrict__ Qin, const float* __restrict__ Kin,
    const float* __restrict__ clusters, const float* __restrict__ W1,
    const float* __restrict__ b1, const float* __restrict__ W2,
    const float* __restrict__ b2) {
    extern __shared__ float smb[];
    float* AT = smb;
    float* BT = smb + 64 * PDT;
    float* WT = smb + 2 * 64 * PDT;
    const int t = threadIdx.x;
    const int h = blockIdx.y;
    const int row0 = blockIdx.x * 64;
    const int isK = blockIdx.z;
    const int ti = t >> 4, tj = t & 15, i0 = ti * 4, o0 = tj * 4;
    const float* src = (isK ? Kin : Qin) + ((size_t)h * NN + row0) * 64;

    for (int i = t; i < 4096; i += 256) {
        AT[(i & 63) * PDT + (i >> 6)] = src[i];
        WT[(i >> 6) * PDT + (i & 63)] = W1[(i & 63) * 64 + (i >> 6)];
    }
    __syncthreads();

    float out[16];
    gemmT(AT, WT, i0, o0, out);
    __syncthreads();
#pragma unroll
    for (int jj = 0; jj < 4; jj++) {
        const float bb = b1[o0 + jj];
        *(float4*)&BT[(o0 + jj) * PDT + i0] = make_float4(
            fmaxf(out[0 * 4 + jj] + bb, 0.f), fmaxf(out[1 * 4 + jj] + bb, 0.f),
            fmaxf(out[2 * 4 + jj] + bb, 0.f), fmaxf(out[3 * 4 + jj] + bb, 0.f));
    }
    for (int i = t; i < 4096; i += 256)
        WT[(i >> 6) * PDT + (i & 63)] = W2[(i & 63) * 64 + (i >> 6)];
    __syncthreads();
    gemmT(BT, WT, i0, o0, out);
    __syncthreads();
#pragma unroll
    for (int jj = 0; jj < 4; jj++) {
        const float bb = b2[o0 + jj];
        *(float4*)&AT[(o0 + jj) * PDT + i0] = make_float4(
            out[0 * 4 + jj] + bb, out[1 * 4 + jj] + bb,
            out[2 * 4 + jj] + bb, out[3 * 4 + jj] + bb);
    }
    for (int i = t; i < 4096; i += 256)
        WT[(i >> 6) * PDT + (i & 63)] = clusters[(size_t)h * 4096 + (i & 63) * 64 + (i >> 6)];
    __syncthreads();
    gemmT(AT, WT, i0, o0, out);
#pragma unroll
    for (int q = 0; q < 16; q++) out[q] = 1.f / (1.f + expf(-out[q]));

    if (isK) {
        // write Khat directly as packed fp16 hi/lo words
#pragma unroll
        for (int ii = 0; ii < 4; ii++) {
            uint32_t h0, l0, h1, l1;
            sp2(out[ii * 4 + 0], out[ii * 4 + 1], h0, l0);
            sp2(out[ii * 4 + 2], out[ii * 4 + 3], h1, l1);
            const size_t wi = ((size_t)h * NN + row0 + i0 + ii) * 32 + (o0 >> 1);
            g_Hhi[wi] = h0; g_Hhi[wi + 1] = h1;
            g_Hlo[wi] = l0; g_Hlo[wi + 1] = l1;
        }
    } else {
        __syncthreads();
#pragma unroll
        for (int jj = 0; jj < 4; jj++)
            *(float4*)&BT[(o0 + jj) * PDT + i0] = make_float4(
                out[0 * 4 + jj], out[1 * 4 + jj], out[2 * 4 + jj], out[3 * 4 + jj]);
        for (int i = t; i < 4096; i += 256)
            WT[(i >> 6) * PDT + (i & 63)] = g_S[(size_t)h * 4096 + i];
        __syncthreads();
        gemmT(BT, WT, i0, o0, out);
#pragma unroll
        for (int ii = 0; ii < 4; ii++)
            *(float4*)&g_T[((size_t)h * NN + row0 + i0 + ii) * 64 + o0] =
                make_float4(out[ii * 4 + 0], out[ii * 4 + 1], out[ii * 4 + 2], out[ii * 4 + 3]);
    }
}

// ============================================================
// Kernel C: fused attention, fp16 m16n8k16 hi/lo splits, double-buffered
// cp.async tiles (pre-packed fp16 operands: no conversion in the loop).
// BM=128, 8 warps x 16-row strips; E stays in registers.
// ============================================================
__global__ void __launch_bounds__(256) k_attn(
    const float* __restrict__ Qg, const int* __restrict__ maskg,
    const float* __restrict__ ug, float* __restrict__ Xout) {
    extern __shared__ float sf[];
    uint32_t* su = (uint32_t*)sf;
    const uint32_t sb4 = (uint32_t)__cvta_generic_to_shared(sf);
    const int t = threadIdx.x, l = t & 31, w = t >> 5;
    const int lg = l >> 2, lt = l & 3;
    const int h = blockIdx.y, row0 = blockIdx.x * BM;

    // ---- prologue 1: Q and T A-fragments (fp16 hi/lo), fragment-major ----
    {
        const float* Qs = Qg + ((size_t)h * NN + row0) * 64;
        const float* Ts = g_T + ((size_t)h * NN + row0) * 64;
        for (int ks = 0; ks < 4; ks++) {
#pragma unroll
            for (int i = 0; i < 4; i++) {
                const int row = 16 * w + lg + 8 * (i & 1);
                const int col = 16 * ks + 2 * lt + 8 * (i >> 1);
                const int fi = ((w * 4 + ks) * 32 + l) * 4 + i;
                const float2 q = *(const float2*)&Qs[row * 64 + col];
                sp2(q.x, q.y, su[F_QHI + fi], su[F_QLO + fi]);
                const float2 tv = *(const float2*)&Ts[row * 64 + col];
                sp2(tv.x, tv.y, su[F_THI + fi], su[F_TLO + fi]);
            }
        }
    }

    // ---- prologue 2: whole-mask ballots (64 words) ----
    for (int g = 0; g < 8; g++) {
        const unsigned bal = __ballot_sync(0xffffffffu, maskg[g * 256 + t] != 0);
        if (l == 0) su[O_MSK + g * 8 + w] = bal;
    }

    // ---- prologue 3: cp.async tile 0 into BUF0 ----
    {
        const uint32_t bbb = sb4 + BUF0 * 4;
#pragma unroll
        for (int r = 0; r < 2; r++) {
            const int wi = t + r * 256;
            const int j = wi >> 3, ck = wi & 7;
            const size_t s = ((size_t)(h * NN + j) << 5) + (ck << 2);
            const uint32_t d = bbb + (j * 36 + (ck << 2)) * 4;
            cp16(d + O_KHI * 4, g_Khi + s);
            cp16(d + O_KLO * 4, g_Klo + s);
            cp16(d + O_HHI * 4, g_Hhi + s);
            cp16(d + O_HLO * 4, g_Hlo + s);
        }
#pragma unroll
        for (int r = 0; r < 2; r++) {
            const int wi = t + r * 256;
            const int jw = wi >> 4, ck = wi & 15;
            const size_t s = ((size_t)(h * (NN / 2) + jw) << 6) + (ck << 2);
            const uint32_t d = bbb + (jw * 68 + (ck << 2)) * 4;
            cp16(d + O_VHI * 4, g_Vhi + s);
            cp16(d + O_VLO * 4, g_Vlo + s);
        }
        CP_COMMIT();
        CP_WAIT0();
    }
    __syncthreads();

    float Co[8][4];
#pragma unroll
    for (int nt = 0; nt < 8; nt++)
#pragma unroll
        for (int q = 0; q < 4; q++) Co[nt][q] = 0.f;
    float Lp0 = 0.f, Lp1 = 0.f;
    unsigned cnt = 0;
    const int gr0 = row0 + 16 * w + lg, gr1 = gr0 + 8;
    const float* u0p = ug + ((size_t)h * NN + gr0) * NN;
    const float* u1p = ug + ((size_t)h * NN + gr1) * NN;

    for (int tile = 0; tile < NTILE; tile++) {
        const int c0 = tile * 64;
        const int bb = (tile & 1) ? BUF1 : BUF0;
        const int nb = (tile & 1) ? BUF0 : BUF1;

        // ---- issue next tile's cp.async (latency hidden under mma) ----
        if (tile + 1 < NTILE) {
            const int c1 = c0 + 64;
            const uint32_t nbb = sb4 + nb * 4;
#pragma unroll
            for (int r = 0; r < 2; r++) {
                const int wi = t + r * 256;
                const int j = wi >> 3, ck = wi & 7;
                const size_t s = ((size_t)(h * NN + c1 + j) << 5) + (ck << 2);
                const uint32_t d = nbb + (j * 36 + (ck << 2)) * 4;
                cp16(d + O_KHI * 4, g_Khi + s);
                cp16(d + O_KLO * 4, g_Klo + s);
                cp16(d + O_HHI * 4, g_Hhi + s);
                cp16(d + O_HLO * 4, g_Hlo + s);
            }
#pragma unroll
            for (int r = 0; r < 2; r++) {
                const int wi = t + r * 256;
                const int jw = wi >> 4, ck = wi & 15;
                const size_t s = ((size_t)(h * (NN / 2) + (c1 >> 1) + jw) << 6) + (ck << 2);
                const uint32_t d = nbb + (jw * 68 + (ck << 2)) * 4;
                cp16(d + O_VHI * 4, g_Vhi + s);
                cp16(d + O_VLO * 4, g_Vlo + s);
            }
            CP_COMMIT();
        }

        // ---- prefetch u ----
        float2 ua[8], ub[8];
#pragma unroll
        for (int nt = 0; nt < 8; nt++) {
            const int jc = c0 + nt * 8 + 2 * lt;
            ua[nt] = *(const float2*)&u0p[jc];
            ub[nt] = *(const float2*)&u1p[jc];
        }

        // ---- S = QK^T (3 products), EA = T Khat^T (4 products) ----
        float Cs[8][4], Ce[8][4];
#pragma unroll
        for (int nt = 0; nt < 8; nt++)
#pragma unroll
            for (int q = 0; q < 4; q++) { Cs[nt][q] = 0.f; Ce[nt][q] = 0.f; }

        for (int ks = 0; ks < 4; ks++) {
            const int fb = ((w * 4 + ks) * 32 + l) * 4;
            const uint4 qh = *(const uint4*)&su[F_QHI + fb];
            const uint4 ql = *(const uint4*)&su[F_QLO + fb];
            const uint4 th = *(const uint4*)&su[F_THI + fb];
            const uint4 tl = *(const uint4*)&su[F_TLO + fb];
#pragma unroll
            for (int hf = 0; hf < 2; hf++) {
                uint32_t kb[4][2], kl[4][2], hb[4][2], hl[4][2];
#pragma unroll
                for (int n = 0; n < 4; n++) {
                    const int jb = bb + ((hf * 4 + n) * 8 + lg) * 36 + 8 * ks + lt;
                    kb[n][0] = su[O_KHI + jb]; kb[n][1] = su[O_KHI + jb + 4];
                    kl[n][0] = su[O_KLO + jb]; kl[n][1] = su[O_KLO + jb + 4];
                    hb[n][0] = su[O_HHI + jb]; hb[n][1] = su[O_HHI + jb + 4];
                    hl[n][0] = su[O_HLO + jb]; hl[n][1] = su[O_HLO + jb + 4];
                }
                float* CsH = &Cs[hf * 4][0];
                float* CeH = &Ce[hf * 4][0];
#pragma unroll
                for (int n = 0; n < 4; n++) mma16(&CsH[n * 4], qh.x, qh.y, qh.z, qh.w, kb[n][0], kb[n][1]);
#pragma unroll
                for (int n = 0; n < 4; n++) mma16(&CeH[n * 4], th.x, th.y, th.z, th.w, hb[n][0], hb[n][1]);
#pragma unroll
                for (int n = 0; n < 4; n++) mma16(&CsH[n * 4], qh.x, qh.y, qh.z, qh.w, kl[n][0], kl[n][1]);
#pragma unroll
                for (int n = 0; n < 4; n++) mma16(&CeH[n * 4], th.x, th.y, th.z, th.w, hl[n][0], hl[n][1]);
#pragma unroll
                for (int n = 0; n < 4; n++) mma16(&CsH[n * 4], ql.x, ql.y, ql.z, ql.w, kb[n][0], kb[n][1]);
#pragma unroll
                for (int n = 0; n < 4; n++) mma16(&CeH[n * 4], tl.x, tl.y, tl.z, tl.w, hb[n][0], hb[n][1]);
#pragma unroll
                for (int n = 0; n < 4; n++) mma16(&CeH[n * 4], tl.x, tl.y, tl.z, tl.w, hl[n][0], hl[n][1]);
            }
        }

        // ---- graph bit + exp; pack E into fp16 hi/lo A-frag pairs (in regs) ----
        const u64 mall = (u64)su[O_MSK + 2 * tile] | ((u64)su[O_MSK + 2 * tile + 1] << 32);
        uint32_t ehi[8][2], elo[8][2];
#pragma unroll
        for (int nt = 0; nt < 8; nt++) {
            const int jc = nt * 8 + 2 * lt;
            const int mA = (int)((mall >> jc) & 1u), mB = (int)((mall >> (jc + 1)) & 1u);
            const unsigned g0 = (ua[nt].x < Ce[nt][0]) ? 1u : 0u;
            const unsigned g1 = (ua[nt].y < Ce[nt][1]) ? 1u : 0u;
            const unsigned g2 = (ub[nt].x < Ce[nt][2]) ? 1u : 0u;
            const unsigned g3 = (ub[nt].y < Ce[nt][3]) ? 1u : 0u;
            cnt += g0 + g1 + g2 + g3;
            const float e0 = (g0 && mA) ? __expf(Cs[nt][0] * 0.125f) : 0.f;
            const float e1 = (g1 && mB) ? __expf(Cs[nt][1] * 0.125f) : 0.f;
            const float e2 = (g2 && mA) ? __expf(Cs[nt][2] * 0.125f) : 0.f;
            const float e3 = (g3 && mB) ? __expf(Cs[nt][3] * 0.125f) : 0.f;
            Lp0 += e0 + e1;
            Lp1 += e2 + e3;
            sp2(e0, e1, ehi[nt][0], elo[nt][0]);   // rows lg
            sp2(e2, e3, ehi[nt][1], elo[nt][1]);   // rows lg+8
        }

        // ---- PV: O += E @ V (3 products), A-frags straight from registers ----
        for (int ks = 0; ks < 4; ks++) {
            const uint32_t ah0 = ehi[2 * ks][0], ah1 = ehi[2 * ks][1];
            const uint32_t ah2 = ehi[2 * ks + 1][0], ah3 = ehi[2 * ks + 1][1];
            const uint32_t al0 = elo[2 * ks][0], al1 = elo[2 * ks][1];
            const uint32_t al2 = elo[2 * ks + 1][0], al3 = elo[2 * ks + 1][1];
#pragma unroll
            for (int hf = 0; hf < 2; hf++) {
                uint32_t vh[4][2], vl[4][2];
#pragma unroll
                for (int n = 0; n < 4; n++) {
                    const int vb = bb + (8 * ks + lt) * 68 + (hf * 4 + n) * 8 + lg;
                    vh[n][0] = su[O_VHI + vb]; vh[n][1] = su[O_VHI + vb + 4 * 68];
                    vl[n][0] = su[O_VLO + vb]; vl[n][1] = su[O_VLO + vb + 4 * 68];
                }
                float* CoH = &Co[hf * 4][0];
#pragma unroll
                for (int n = 0; n < 4; n++) mma16(&CoH[n * 4], ah0, ah1, ah2, ah3, vh[n][0], vh[n][1]);
#pragma unroll
                for (int n = 0; n < 4; n++) mma16(&CoH[n * 4], ah0, ah1, ah2, ah3, vl[n][0], vl[n][1]);
#pragma unroll
                for (int n = 0; n < 4; n++) mma16(&CoH[n * 4], al0, al1, al2, al3, vh[n][0], vh[n][1]);
            }
        }

        if (tile + 1 < NTILE) CP_WAIT0();
        __syncthreads();
    }

    // ---- epilogue: L reduce over quad lanes, write X = O / L ----
    Lp0 += __shfl_xor_sync(0xffffffffu, Lp0, 1);
    Lp0 += __shfl_xor_sync(0xffffffffu, Lp0, 2);
    Lp1 += __shfl_xor_sync(0xffffffffu, Lp1, 1);
    Lp1 += __shfl_xor_sync(0xffffffffu, Lp1, 2);
    const float r0 = (Lp0 > 0.f) ? (1.f / Lp0) : 0.f;
    const float r1 = (Lp1 > 0.f) ? (1.f / Lp1) : 0.f;
    float* X0 = Xout + ((size_t)h * NN + gr0) * 64;
    float* X1 = Xout + ((size_t)h * NN + gr1) * 64;
#pragma unroll
    for (int nt = 0; nt < 8; nt++) {
        const int jc = nt * 8 + 2 * lt;
        *(float2*)&X0[jc] = make_float2(Co[nt][0] * r0, Co[nt][1] * r0);
        *(float2*)&X1[jc] = make_float2(Co[nt][2] * r1, Co[nt][3] * r1);
    }

    // ---- sparsity popcount ----
#pragma unroll
    for (int off = 16; off > 0; off >>= 1) cnt += __shfl_xor_sync(0xffffffffu, cnt, off);
    if (l == 0) su[O_CNT + w] = cnt;
    __syncthreads();
    if (t == 0) {
        unsigned tot = 0;
#pragma unroll
        for (int i = 0; i < 8; i++) tot += su[O_CNT + i];
        atomicAdd(&g_cnt[h], tot);
    }
}

// ============================================================
__global__ void k_spars(float* __restrict__ out) {
    const int h = threadIdx.x;
    if (h < NH) out[h] = (float)g_cnt[h] * (1.0f / ((float)NN * (float)NN));
}

// ============================================================
extern "C" void kernel_launch(void* const* d_in, const int* in_sizes, int n_in,
                              void* d_out, int out_size) {
    (void)in_sizes; (void)n_in;
    const float* Q        = (const float*)d_in[0];
    const float* K        = (const float*)d_in[1];
    const float* V        = (const float*)d_in[2];
    const int*   mask     = (const int*)d_in[3];
    const float* u        = (const float*)d_in[4];
    const float* clusters = (const float*)d_in[5];
    const float* W1       = (const float*)d_in[6];
    const float* b1       = (const float*)d_in[7];
    const float* W2       = (const float*)d_in[8];
    const float* b2       = (const float*)d_in[9];
    float* X = (float*)d_out;
    float* spars = X + (out_size - NH);

    const int SMB = 3 * 64 * PDT * 4;
    cudaFuncSetAttribute(k_projhat, cudaFuncAttributeMaxDynamicSharedMemorySize, SMB);
    cudaFuncSetAttribute(k_attn, cudaFuncAttributeMaxDynamicSharedMemorySize, SMEM_ATTN);

    k_clusterS<<<NH, 256>>>(clusters);
    k_prep<<<2048, 256>>>(K, V);
    k_projhat<<<dim3(NN / 64, NH, 2), 256, SMB>>>(Q, K, clusters, W1, b1, W2, b2);
    k_attn<<<dim3(NN / BM, NH), 256, SMEM_ATTN>>>(Q, mask, u, X);
    k_spars<<<1, NH>>>(spars);
}